// round 13
// baseline (speedup 1.0000x reference)
#include <cuda_runtime.h>
#include <math.h>

#define B_MAX    4000000
#define BLOCKS   740        // 148 SMs * 5, all co-resident (required for barrier)
#define NTHREADS 256
#define CHUNK    5408       // multiple of 32; 740*5408 >= 4M
#define TILE     256

__device__ float             g_blockmax[BLOCKS];
__device__ float             g_partials[BLOCKS];
__device__ unsigned int      g_bar_count = 0;
__device__ volatile unsigned g_bar_flag  = 0;
__device__ unsigned int      g_ticket    = 0;

// ---------------------------------------------------------------------------
__device__ __forceinline__ float rsqrt_ap(float x) {
    float y; asm("rsqrt.approx.f32 %0, %1;" : "=f"(y) : "f"(x)); return y;
}
__device__ __forceinline__ float rcp_ap(float x) {
    float y; asm("rcp.approx.f32 %0, %1;" : "=f"(y) : "f"(x)); return y;
}
__device__ __forceinline__ float sqrt_ap(float x) {
    float y; asm("sqrt.approx.f32 %0, %1;" : "=f"(y) : "f"(x)); return y;
}
__device__ __forceinline__ float ex2_ap(float x) {
    float y; asm("ex2.approx.f32 %0, %1;" : "=f"(y) : "f"(x)); return y;
}
__device__ __forceinline__ float lg2_ap(float x) {
    float y; asm("lg2.approx.f32 %0, %1;" : "=f"(y) : "f"(x)); return y;
}
__device__ __forceinline__ void cp16(void* sdst, const void* gsrc) {
    unsigned saddr = (unsigned)__cvta_generic_to_shared(sdst);
    asm volatile("cp.async.ca.shared.global [%0], [%1], 16;" :: "r"(saddr), "l"(gsrc));
}

// ---------------------------------------------------------------------------
// Lean compensated sincos for |x| <= pi+eps. Abs error ~2^-26.5 (sin) /
// 2^-27.8 (cos) — calibrated: costs ~0.8e-4 of rel_err vs correctly-rounded.
__device__ __forceinline__ void lean_sincos(float x, float& s_out, float& c_out) {
    const float TWO_OVER_PI = 0.63661977236758134f;
    const float C1 = 1.57079637050628662109375f;   // float(pi/2)
    const float C2 = -4.37113900018624283e-8f;     // pi/2 - C1 (rounded)

    float qf = rintf(x * TWO_OVER_PI);             // q in {-2..2}
    int   n  = (int)qf;

    float a   = fmaf(qf, -C1, x);                  // exact
    float b   = -qf * C2;
    float rhi = a + b;
    float t0  = rhi - a;
    float rlo = b - t0;                            // Fast2Sum low word

    float r2h = rhi * rhi;
    float r2l = fmaf(rhi, rhi, -r2h);              // exact low part of rhi^2

    // ---- sin(rhi) + rlo*cos(rhi) ----
    const float c11 = -2.50521083854417202e-8f;
    const float c9  =  2.75573192239858907e-6f;
    const float c7  = -1.98412698412698413e-4f;
    const float c5  =  8.33333333333333333e-3f;
    const float c3  = -0.16666667163372039794921875f;

    float U  = fmaf(r2h, c11, c9);
    U        = fmaf(r2h, U, c7);
    U        = fmaf(r2h, U, c5);
    float vh = fmaf(r2h, U, c3);                   // V(r^2)
    float wh = r2h * rhi;                          // r^3
    float hh = 0.5f * r2h;                         // exact
    float rloc = fmaf(-hh, rlo, rlo);              // rlo*cos(rhi) approx
    float stail = fmaf(wh, vh, rloc);
    float sinr  = rhi + stail;

    // ---- cos(rhi) - rhi*rlo ----
    const float e10 = -2.75573192239858907e-7f;
    const float e8  =  2.48015873015873016e-5f;
    const float e6  = -1.38888888888888889e-3f;
    const float c4  =  0.041666667908430099487304688f;

    float F  = fmaf(r2h, e10, e8);
    F        = fmaf(r2h, F, e6);
    float Eh = fmaf(r2h, F, c4);                   // E(r^2)
    float r4h = r2h * r2h;
    float Ah  = 1.0f - hh;
    float Al  = (1.0f - Ah) - hh;                  // exact Fast2Sum
    float ctail = fmaf(r4h, Eh, Al);
    ctail = fmaf(-0.5f, r2l, ctail);
    ctail = fmaf(-rhi, rlo, ctail);
    float cosr = Ah + ctail;

    // ---- quadrant fixup ----
    int m = n & 3;
    float s = (m & 1) ? cosr : sinr;
    float c = (m & 1) ? sinr : cosr;
    if (m & 2)       s = -s;
    if ((m + 1) & 2) c = -c;
    s_out = s;
    c_out = c;
}

// ---------------------------------------------------------------------------
// Per-point ENU distance: geodetic (from smem) + pred ECEF (registers).
__device__ __forceinline__ float enu_dist_r(float px, float py, float pz,
                                            float lat, float lon, float h) {
    const float DEG2RAD = 0.017453292519943295f;
    const float E2      = 0.00669437999014f;
    const float A       = 6378137.0f;
    const float C1mE2   = 0.99330562000986f;

    float latr = __fmul_rn(lat, DEG2RAD);
    float lonr = __fmul_rn(lon, DEG2RAD);

    float sl, cl, so, co;
    lean_sincos(latr, sl, cl);
    lean_sincos(lonr, so, co);

    // t = 1 - ((E2*sl)*sl)  (exact reference association)
    float t = __fsub_rn(1.0f, __fmul_rn(__fmul_rn(E2, sl), sl));

    // s = rn(sqrt(t)) via rsqrt + exact-residual Newton (mismatch p ~ 2^-18)
    float y0 = rsqrt_ap(t);
    float s0 = __fmul_rn(t, y0);
    float es = __fmaf_rn(s0, s0, -t);
    float hlf = __fmul_rn(0.5f, y0);
    float s  = __fmaf_rn(es, -hlf, s0);

    // N = rn(A / s) via rcp + exact-residual Newton (mismatch p ~ 2^-18)
    float r0 = rcp_ap(s);
    float q0 = __fmul_rn(A, r0);
    float eq = __fmaf_rn(q0, s, -A);
    float N  = __fmaf_rn(eq, -r0, q0);

    float Nh = __fadd_rn(N, h);
    float Nhcl = __fmul_rn(Nh, cl);
    float rx = __fmul_rn(Nhcl, co);
    float ry = __fmul_rn(Nhcl, so);
    float rz = __fmul_rn(__fadd_rn(__fmul_rn(N, C1mE2), h), sl);

    float dx = __fsub_rn(px, rx);
    float dy = __fsub_rn(py, ry);
    float dz = __fsub_rn(pz, rz);

    float e = -so * dx + co * dy;
    float n = -sl * co * dx - sl * so * dy + cl * dz;
    float u =  cl * co * dx + cl * so * dy + sl * dz;

    return sqrt_ap(e * e + n * n + u * u);
}

// ---------------------------------------------------------------------------
// Fused persistent kernel: cp.async triple-buffered tgt staging; inp prefetched
// one tile ahead into registers (full tile of LDG latency slack).
__global__ void __launch_bounds__(NTHREADS, 5)
k_fused(const float* __restrict__ inp, const float* __restrict__ tgt,
        float* __restrict__ out, int B) {
    __shared__ float s_dist[CHUNK];
    __shared__ float s_tgt[3][TILE * 3];
    __shared__ float s_red[NTHREADS / 32];

    int start = blockIdx.x * CHUNK;
    int cnt   = min(CHUNK, B - start);
    if (cnt < 0) cnt = 0;
    int ntiles = (cnt + TILE - 1) / TILE;

    int lane = threadIdx.x & 31, wid = threadIdx.x >> 5;

    // ---------------- Phase 1: pipelined distances -> smem ----------------
    // stage tgt tile 0 + prefetch inp tile 0 into registers
    float px = 0.0f, py = 0.0f, pz = 0.0f;
    if (ntiles > 0) {
        int pc  = min(TILE, cnt);
        int nf4 = (pc * 3) >> 2;
        const float* gt = tgt + 3 * start;
        for (int i = threadIdx.x; i < nf4; i += NTHREADS)
            cp16(&s_tgt[0][i * 4], gt + i * 4);
        int k0 = threadIdx.x;
        if (k0 < cnt) {
            const float* gp = inp + 3 * (start + k0);
            px = gp[0]; py = gp[1]; pz = gp[2];
        }
    }
    asm volatile("cp.async.commit_group;");

    float local_max = 0.0f;
    for (int t = 0; t < ntiles; t++) {
        // prefetch next tile: tgt -> smem (cp.async), inp -> registers
        float nx = 0.0f, ny = 0.0f, nz = 0.0f;
        if (t + 1 < ntiles) {
            int p0  = (t + 1) * TILE;
            int pc  = min(TILE, cnt - p0);
            int nf4 = (pc * 3) >> 2;
            int bs  = (t + 1) % 3;
            const float* gt = tgt + 3 * (start + p0);
            for (int i = threadIdx.x; i < nf4; i += NTHREADS)
                cp16(&s_tgt[bs][i * 4], gt + i * 4);
            asm volatile("cp.async.commit_group;");
            int k1 = p0 + threadIdx.x;
            if (k1 < cnt) {
                const float* gp = inp + 3 * (start + k1);
                nx = gp[0]; ny = gp[1]; nz = gp[2];
            }
            asm volatile("cp.async.wait_group 1;");
        } else {
            asm volatile("cp.async.wait_group 0;");
        }
        __syncthreads();                            // single sync (triple buffer)

        int k = t * TILE + threadIdx.x;
        if (k < cnt) {
            int b = t % 3;
            int j = threadIdx.x * 3;
            float d = enu_dist_r(px, py, pz,
                                 s_tgt[b][j], s_tgt[b][j + 1], s_tgt[b][j + 2]);
            s_dist[k] = d;
            local_max = fmaxf(local_max, d);
        }
        px = nx; py = ny; pz = nz;
    }

    #pragma unroll
    for (int o = 16; o > 0; o >>= 1)
        local_max = fmaxf(local_max, __shfl_xor_sync(0xFFFFFFFFu, local_max, o));
    if (lane == 0) s_red[wid] = local_max;
    __syncthreads();
    if (wid == 0) {
        float v = (lane < NTHREADS / 32) ? s_red[lane] : 0.0f;
        #pragma unroll
        for (int o = 16; o > 0; o >>= 1)
            v = fmaxf(v, __shfl_xor_sync(0xFFFFFFFFu, v, o));
        if (lane == 0) g_blockmax[blockIdx.x] = v;
    }

    // ---------------- Grid barrier (flag-flip, replay-safe) ----------------
    __threadfence();
    if (threadIdx.x == 0) {
        unsigned f = g_bar_flag;
        unsigned arrived = atomicAdd(&g_bar_count, 1u);
        if (arrived == BLOCKS - 1) {
            g_bar_count = 0;
            __threadfence();
            g_bar_flag = f ^ 1u;
        } else {
            while (g_bar_flag == f) { }
        }
    }
    __syncthreads();
    __threadfence();

    // ---------------- Global max (every block, fixed order) ----------------
    float m = 0.0f;
    for (int i = threadIdx.x; i < BLOCKS; i += NTHREADS)
        m = fmaxf(m, g_blockmax[i]);
    #pragma unroll
    for (int o = 16; o > 0; o >>= 1)
        m = fmaxf(m, __shfl_xor_sync(0xFFFFFFFFu, m, o));
    if (lane == 0) s_red[wid] = m;
    __syncthreads();
    if (wid == 0) {
        float v = (lane < NTHREADS / 32) ? s_red[lane] : 0.0f;
        #pragma unroll
        for (int o = 16; o > 0; o >>= 1)
            v = fmaxf(v, __shfl_xor_sync(0xFFFFFFFFu, v, o));
        if (lane == 0) s_red[0] = v;
    }
    __syncthreads();
    float inv_denom = 1.0f / __fadd_rn(s_red[0], 1e-8f);
    __syncthreads();

    // ---------------- Phase 2: focal loss from smem ----------------
    const float L2E = 1.4426950408889634f;          // log2(e)
    float sum = 0.0f;
    for (int i = threadIdx.x; i < cnt; i += NTHREADS) {
        float d    = s_dist[i];
        float g    = ex2_ap(fmaf(-L2E, d, 1.0f));   // 2*exp(-d)
        float base = 1.0f - sqrt_ap(d * inv_denom);
        float w    = ex2_ap(g * lg2_ap(base));      // base^g
        float fl   = w * d;
        sum += fl * fl;
    }

    #pragma unroll
    for (int o = 16; o > 0; o >>= 1)
        sum += __shfl_xor_sync(0xFFFFFFFFu, sum, o);
    if (lane == 0) s_red[wid] = sum;
    __syncthreads();
    if (wid == 0) {
        float v = (lane < NTHREADS / 32) ? s_red[lane] : 0.0f;
        #pragma unroll
        for (int o = 16; o > 0; o >>= 1)
            v += __shfl_xor_sync(0xFFFFFFFFu, v, o);
        if (lane == 0) g_partials[blockIdx.x] = v;
    }

    // ---------------- Last block finishes (deterministic) ----------------
    __shared__ unsigned s_ticket;
    __threadfence();
    if (threadIdx.x == 0)
        s_ticket = atomicAdd(&g_ticket, 1u);
    __syncthreads();
    if (s_ticket == BLOCKS - 1) {
        __threadfence();
        float fs = 0.0f;
        for (int i = threadIdx.x; i < BLOCKS; i += NTHREADS)
            fs += g_partials[i];
        #pragma unroll
        for (int o = 16; o > 0; o >>= 1)
            fs += __shfl_xor_sync(0xFFFFFFFFu, fs, o);
        __syncthreads();
        if (lane == 0) s_red[wid] = fs;
        __syncthreads();
        if (wid == 0) {
            float v = (lane < NTHREADS / 32) ? s_red[lane] : 0.0f;
            #pragma unroll
            for (int o = 16; o > 0; o >>= 1)
                v += __shfl_xor_sync(0xFFFFFFFFu, v, o);
            if (lane == 0) {
                out[0] = sqrtf(v / (float)B);
                g_ticket = 0;
            }
        }
    }
}

// ---------------------------------------------------------------------------
extern "C" void kernel_launch(void* const* d_in, const int* in_sizes, int n_in,
                              void* d_out, int out_size) {
    const float* inp = (const float*)d_in[0];   // (B,3) pred ECEF
    const float* tgt = (const float*)d_in[1];   // (B,3) lat/lon/h
    int B = in_sizes[0] / 3;
    float* out = (float*)d_out;

    k_fused<<<BLOCKS, NTHREADS>>>(inp, tgt, out, B);
}

// round 14
// speedup vs baseline: 1.1050x; 1.1050x over previous
#include <cuda_runtime.h>
#include <math.h>

#define B_MAX    4000000
#define BLOCKS   592        // 148 SMs * 4, all co-resident (required for barrier)
#define NTHREADS 256
#define CHUNK    6784       // multiple of 4 -> 16B staging alignment; 592*6784 >= 4M
#define TILE     512        // 2 points per thread per tile

__device__ float             g_blockmax[BLOCKS];
__device__ float             g_partials[BLOCKS];
__device__ unsigned int      g_bar_count = 0;
__device__ volatile unsigned g_bar_flag  = 0;
__device__ unsigned int      g_ticket    = 0;

// ---------------------------------------------------------------------------
__device__ __forceinline__ float rsqrt_ap(float x) {
    float y; asm("rsqrt.approx.f32 %0, %1;" : "=f"(y) : "f"(x)); return y;
}
__device__ __forceinline__ float rcp_ap(float x) {
    float y; asm("rcp.approx.f32 %0, %1;" : "=f"(y) : "f"(x)); return y;
}
__device__ __forceinline__ float sqrt_ap(float x) {
    float y; asm("sqrt.approx.f32 %0, %1;" : "=f"(y) : "f"(x)); return y;
}
__device__ __forceinline__ float ex2_ap(float x) {
    float y; asm("ex2.approx.f32 %0, %1;" : "=f"(y) : "f"(x)); return y;
}
__device__ __forceinline__ float lg2_ap(float x) {
    float y; asm("lg2.approx.f32 %0, %1;" : "=f"(y) : "f"(x)); return y;
}
__device__ __forceinline__ void cp16(void* sdst, const void* gsrc) {
    unsigned saddr = (unsigned)__cvta_generic_to_shared(sdst);
    asm volatile("cp.async.ca.shared.global [%0], [%1], 16;" :: "r"(saddr), "l"(gsrc));
}

// ---------------------------------------------------------------------------
// Lean compensated sincos for |x| <= pi+eps. Abs error ~2^-26.5 (sin) /
// 2^-27.8 (cos) — calibrated: costs ~0.8e-4 of rel_err vs correctly-rounded.
__device__ __forceinline__ void lean_sincos(float x, float& s_out, float& c_out) {
    const float TWO_OVER_PI = 0.63661977236758134f;
    const float C1 = 1.57079637050628662109375f;   // float(pi/2)
    const float C2 = -4.37113900018624283e-8f;     // pi/2 - C1 (rounded)

    float qf = rintf(x * TWO_OVER_PI);             // q in {-2..2}
    int   n  = (int)qf;

    float a   = fmaf(qf, -C1, x);                  // exact
    float b   = -qf * C2;
    float rhi = a + b;
    float t0  = rhi - a;
    float rlo = b - t0;                            // Fast2Sum low word

    float r2h = rhi * rhi;
    float r2l = fmaf(rhi, rhi, -r2h);              // exact low part of rhi^2

    // ---- sin(rhi) + rlo*cos(rhi) ----
    const float c11 = -2.50521083854417202e-8f;
    const float c9  =  2.75573192239858907e-6f;
    const float c7  = -1.98412698412698413e-4f;
    const float c5  =  8.33333333333333333e-3f;
    const float c3  = -0.16666667163372039794921875f;

    float U  = fmaf(r2h, c11, c9);
    U        = fmaf(r2h, U, c7);
    U        = fmaf(r2h, U, c5);
    float vh = fmaf(r2h, U, c3);                   // V(r^2)
    float wh = r2h * rhi;                          // r^3
    float hh = 0.5f * r2h;                         // exact
    float rloc = fmaf(-hh, rlo, rlo);              // rlo*cos(rhi) approx
    float stail = fmaf(wh, vh, rloc);
    float sinr  = rhi + stail;

    // ---- cos(rhi) - rhi*rlo ----
    const float e10 = -2.75573192239858907e-7f;
    const float e8  =  2.48015873015873016e-5f;
    const float e6  = -1.38888888888888889e-3f;
    const float c4  =  0.041666667908430099487304688f;

    float F  = fmaf(r2h, e10, e8);
    F        = fmaf(r2h, F, e6);
    float Eh = fmaf(r2h, F, c4);                   // E(r^2)
    float r4h = r2h * r2h;
    float Ah  = 1.0f - hh;
    float Al  = (1.0f - Ah) - hh;                  // exact Fast2Sum
    float ctail = fmaf(r4h, Eh, Al);
    ctail = fmaf(-0.5f, r2l, ctail);
    ctail = fmaf(-rhi, rlo, ctail);
    float cosr = Ah + ctail;

    // ---- quadrant fixup ----
    int m = n & 3;
    float s = (m & 1) ? cosr : sinr;
    float c = (m & 1) ? sinr : cosr;
    if (m & 2)       s = -s;
    if ((m + 1) & 2) c = -c;
    s_out = s;
    c_out = c;
}

// ---------------------------------------------------------------------------
// Per-point ENU distance from smem-staged data (3 floats each).
__device__ __forceinline__ float enu_dist_s(const float* __restrict__ sp,
                                            const float* __restrict__ st) {
    const float DEG2RAD = 0.017453292519943295f;
    const float E2      = 0.00669437999014f;
    const float A       = 6378137.0f;
    const float C1mE2   = 0.99330562000986f;

    float lat = st[0], lon = st[1], h = st[2];

    float latr = __fmul_rn(lat, DEG2RAD);
    float lonr = __fmul_rn(lon, DEG2RAD);

    float sl, cl, so, co;
    lean_sincos(latr, sl, cl);
    lean_sincos(lonr, so, co);

    // t = 1 - ((E2*sl)*sl)  (exact reference association)
    float t = __fsub_rn(1.0f, __fmul_rn(__fmul_rn(E2, sl), sl));

    // s = rn(sqrt(t)) via rsqrt + exact-residual Newton (mismatch p ~ 2^-18)
    float y0 = rsqrt_ap(t);
    float s0 = __fmul_rn(t, y0);
    float es = __fmaf_rn(s0, s0, -t);
    float hlf = __fmul_rn(0.5f, y0);
    float s  = __fmaf_rn(es, -hlf, s0);

    // N = rn(A / s) via rcp + exact-residual Newton (mismatch p ~ 2^-18)
    float r0 = rcp_ap(s);
    float q0 = __fmul_rn(A, r0);
    float eq = __fmaf_rn(q0, s, -A);
    float N  = __fmaf_rn(eq, -r0, q0);

    float Nh = __fadd_rn(N, h);
    float Nhcl = __fmul_rn(Nh, cl);
    float rx = __fmul_rn(Nhcl, co);
    float ry = __fmul_rn(Nhcl, so);
    float rz = __fmul_rn(__fadd_rn(__fmul_rn(N, C1mE2), h), sl);

    float dx = __fsub_rn(sp[0], rx);
    float dy = __fsub_rn(sp[1], ry);
    float dz = __fsub_rn(sp[2], rz);

    float e = -so * dx + co * dy;
    float n = -sl * co * dx - sl * so * dy + cl * dz;
    float u =  cl * co * dx + cl * so * dy + sl * dz;

    return sqrt_ap(e * e + n * n + u * u);
}

// ---------------------------------------------------------------------------
// Fused persistent kernel (round-11 pipeline structure, 512-pt tiles):
// cp.async double-buffered staging of BOTH arrays, 2 points/thread/tile,
// grid barrier for global max, focal sum, deterministic last-block finish.
__global__ void __launch_bounds__(NTHREADS, 4)
k_fused(const float* __restrict__ inp, const float* __restrict__ tgt,
        float* __restrict__ out, int B) {
    __shared__ float s_dist[CHUNK];
    __shared__ float s_tgt[2][TILE * 3];
    __shared__ float s_inp[2][TILE * 3];
    __shared__ float s_red[NTHREADS / 32];

    int start = blockIdx.x * CHUNK;
    int cnt   = min(CHUNK, B - start);
    if (cnt < 0) cnt = 0;
    int ntiles = (cnt + TILE - 1) / TILE;

    int lane = threadIdx.x & 31, wid = threadIdx.x >> 5;

    // ---------------- Phase 1: pipelined distances -> smem ----------------
    if (ntiles > 0) {
        int pc  = min(TILE, cnt);
        int nf4 = (pc * 3) >> 2;                    // pc multiple of 4
        const float* gt = tgt + 3 * start;
        const float* gi = inp + 3 * start;
        for (int i = threadIdx.x; i < nf4; i += NTHREADS) {
            cp16(&s_tgt[0][i * 4], gt + i * 4);
            cp16(&s_inp[0][i * 4], gi + i * 4);
        }
    }
    asm volatile("cp.async.commit_group;");

    float local_max = 0.0f;
    for (int t = 0; t < ntiles; t++) {
        if (t + 1 < ntiles) {
            int p0  = (t + 1) * TILE;
            int pc  = min(TILE, cnt - p0);
            int nf4 = (pc * 3) >> 2;
            int bs  = (t + 1) & 1;
            const float* gt = tgt + 3 * (start + p0);
            const float* gi = inp + 3 * (start + p0);
            for (int i = threadIdx.x; i < nf4; i += NTHREADS) {
                cp16(&s_tgt[bs][i * 4], gt + i * 4);
                cp16(&s_inp[bs][i * 4], gi + i * 4);
            }
            asm volatile("cp.async.commit_group;");
            asm volatile("cp.async.wait_group 1;");
        } else {
            asm volatile("cp.async.wait_group 0;");
        }
        __syncthreads();                            // tile t visible to all

        int b  = t & 1;
        int k0 = t * TILE + threadIdx.x;            // point 0
        int k1 = k0 + NTHREADS;                     // point 1 (independent)
        if (k0 < cnt) {
            int j = threadIdx.x * 3;
            float d = enu_dist_s(&s_inp[b][j], &s_tgt[b][j]);
            s_dist[k0] = d;
            local_max = fmaxf(local_max, d);
        }
        if (k1 < cnt) {
            int j = (threadIdx.x + NTHREADS) * 3;
            float d = enu_dist_s(&s_inp[b][j], &s_tgt[b][j]);
            s_dist[k1] = d;
            local_max = fmaxf(local_max, d);
        }
        __syncthreads();                            // done reading buf before t+2 stage
    }

    #pragma unroll
    for (int o = 16; o > 0; o >>= 1)
        local_max = fmaxf(local_max, __shfl_xor_sync(0xFFFFFFFFu, local_max, o));
    if (lane == 0) s_red[wid] = local_max;
    __syncthreads();
    if (wid == 0) {
        float v = (lane < NTHREADS / 32) ? s_red[lane] : 0.0f;
        #pragma unroll
        for (int o = 16; o > 0; o >>= 1)
            v = fmaxf(v, __shfl_xor_sync(0xFFFFFFFFu, v, o));
        if (lane == 0) g_blockmax[blockIdx.x] = v;
    }

    // ---------------- Grid barrier (flag-flip, replay-safe) ----------------
    __threadfence();
    if (threadIdx.x == 0) {
        unsigned f = g_bar_flag;
        unsigned arrived = atomicAdd(&g_bar_count, 1u);
        if (arrived == BLOCKS - 1) {
            g_bar_count = 0;
            __threadfence();
            g_bar_flag = f ^ 1u;
        } else {
            while (g_bar_flag == f) { }
        }
    }
    __syncthreads();
    __threadfence();

    // ---------------- Global max (every block, fixed order) ----------------
    float m = 0.0f;
    for (int i = threadIdx.x; i < BLOCKS; i += NTHREADS)
        m = fmaxf(m, g_blockmax[i]);
    #pragma unroll
    for (int o = 16; o > 0; o >>= 1)
        m = fmaxf(m, __shfl_xor_sync(0xFFFFFFFFu, m, o));
    if (lane == 0) s_red[wid] = m;
    __syncthreads();
    if (wid == 0) {
        float v = (lane < NTHREADS / 32) ? s_red[lane] : 0.0f;
        #pragma unroll
        for (int o = 16; o > 0; o >>= 1)
            v = fmaxf(v, __shfl_xor_sync(0xFFFFFFFFu, v, o));
        if (lane == 0) s_red[0] = v;
    }
    __syncthreads();
    float inv_denom = 1.0f / __fadd_rn(s_red[0], 1e-8f);
    __syncthreads();

    // ---------------- Phase 2: focal loss from smem ----------------
    const float L2E = 1.4426950408889634f;          // log2(e)
    float sum = 0.0f;
    for (int i = threadIdx.x; i < cnt; i += NTHREADS) {
        float d    = s_dist[i];
        float g    = ex2_ap(fmaf(-L2E, d, 1.0f));   // 2*exp(-d)
        float base = 1.0f - sqrt_ap(d * inv_denom);
        float w    = ex2_ap(g * lg2_ap(base));      // base^g
        float fl   = w * d;
        sum += fl * fl;
    }

    #pragma unroll
    for (int o = 16; o > 0; o >>= 1)
        sum += __shfl_xor_sync(0xFFFFFFFFu, sum, o);
    if (lane == 0) s_red[wid] = sum;
    __syncthreads();
    if (wid == 0) {
        float v = (lane < NTHREADS / 32) ? s_red[lane] : 0.0f;
        #pragma unroll
        for (int o = 16; o > 0; o >>= 1)
            v += __shfl_xor_sync(0xFFFFFFFFu, v, o);
        if (lane == 0) g_partials[blockIdx.x] = v;
    }

    // ---------------- Last block finishes (deterministic) ----------------
    __shared__ unsigned s_ticket;
    __threadfence();
    if (threadIdx.x == 0)
        s_ticket = atomicAdd(&g_ticket, 1u);
    __syncthreads();
    if (s_ticket == BLOCKS - 1) {
        __threadfence();
        float fs = 0.0f;
        for (int i = threadIdx.x; i < BLOCKS; i += NTHREADS)
            fs += g_partials[i];
        #pragma unroll
        for (int o = 16; o > 0; o >>= 1)
            fs += __shfl_xor_sync(0xFFFFFFFFu, fs, o);
        __syncthreads();
        if (lane == 0) s_red[wid] = fs;
        __syncthreads();
        if (wid == 0) {
            float v = (lane < NTHREADS / 32) ? s_red[lane] : 0.0f;
            #pragma unroll
            for (int o = 16; o > 0; o >>= 1)
                v += __shfl_xor_sync(0xFFFFFFFFu, v, o);
            if (lane == 0) {
                out[0] = sqrtf(v / (float)B);
                g_ticket = 0;
            }
        }
    }
}

// ---------------------------------------------------------------------------
extern "C" void kernel_launch(void* const* d_in, const int* in_sizes, int n_in,
                              void* d_out, int out_size) {
    const float* inp = (const float*)d_in[0];   // (B,3) pred ECEF
    const float* tgt = (const float*)d_in[1];   // (B,3) lat/lon/h
    int B = in_sizes[0] / 3;
    float* out = (float*)d_out;

    k_fused<<<BLOCKS, NTHREADS>>>(inp, tgt, out, B);
}

// round 15
// speedup vs baseline: 1.1633x; 1.0527x over previous
#include <cuda_runtime.h>
#include <math.h>

#define B_MAX    4000000
#define BLOCKS   592        // 148 SMs * 4, all co-resident (required for barrier)
#define NTHREADS 256
#define CHUNK    6784       // multiple of 4 -> 16B staging alignment; 592*6784 >= 4M
#define TILE     512        // 2 points per thread per tile

__device__ float             g_blockmax[BLOCKS];
__device__ float             g_partials[BLOCKS];
__device__ unsigned int      g_bar_count = 0;
__device__ volatile unsigned g_bar_flag  = 0;
__device__ unsigned int      g_ticket    = 0;

// ---------------------------------------------------------------------------
__device__ __forceinline__ float rsqrt_ap(float x) {
    float y; asm("rsqrt.approx.f32 %0, %1;" : "=f"(y) : "f"(x)); return y;
}
__device__ __forceinline__ float rcp_ap(float x) {
    float y; asm("rcp.approx.f32 %0, %1;" : "=f"(y) : "f"(x)); return y;
}
__device__ __forceinline__ float sqrt_ap(float x) {
    float y; asm("sqrt.approx.f32 %0, %1;" : "=f"(y) : "f"(x)); return y;
}
__device__ __forceinline__ float ex2_ap(float x) {
    float y; asm("ex2.approx.f32 %0, %1;" : "=f"(y) : "f"(x)); return y;
}
__device__ __forceinline__ float lg2_ap(float x) {
    float y; asm("lg2.approx.f32 %0, %1;" : "=f"(y) : "f"(x)); return y;
}
__device__ __forceinline__ void cp16(void* sdst, const void* gsrc) {
    unsigned saddr = (unsigned)__cvta_generic_to_shared(sdst);
    asm volatile("cp.async.ca.shared.global [%0], [%1], 16;" :: "r"(saddr), "l"(gsrc));
}

// ---------------------------------------------------------------------------
// Lean compensated sincos for |x| <= pi+eps. Abs error ~2^-26.5 (sin) /
// 2^-27.8 (cos) — calibrated: costs ~0.8e-4 of rel_err vs correctly-rounded.
__device__ __forceinline__ void lean_sincos(float x, float& s_out, float& c_out) {
    const float TWO_OVER_PI = 0.63661977236758134f;
    const float C1 = 1.57079637050628662109375f;   // float(pi/2)
    const float C2 = -4.37113900018624283e-8f;     // pi/2 - C1 (rounded)

    float qf = rintf(x * TWO_OVER_PI);             // q in {-2..2}
    int   n  = (int)qf;

    float a   = fmaf(qf, -C1, x);                  // exact
    float b   = -qf * C2;
    float rhi = a + b;
    float t0  = rhi - a;
    float rlo = b - t0;                            // Fast2Sum low word

    float r2h = rhi * rhi;
    float r2l = fmaf(rhi, rhi, -r2h);              // exact low part of rhi^2

    // ---- sin(rhi) + rlo*cos(rhi) ----
    const float c11 = -2.50521083854417202e-8f;
    const float c9  =  2.75573192239858907e-6f;
    const float c7  = -1.98412698412698413e-4f;
    const float c5  =  8.33333333333333333e-3f;
    const float c3  = -0.16666667163372039794921875f;

    float U  = fmaf(r2h, c11, c9);
    U        = fmaf(r2h, U, c7);
    U        = fmaf(r2h, U, c5);
    float vh = fmaf(r2h, U, c3);                   // V(r^2)
    float wh = r2h * rhi;                          // r^3
    float hh = 0.5f * r2h;                         // exact
    float rloc = fmaf(-hh, rlo, rlo);              // rlo*cos(rhi) approx
    float stail = fmaf(wh, vh, rloc);
    float sinr  = rhi + stail;

    // ---- cos(rhi) - rhi*rlo ----
    const float e10 = -2.75573192239858907e-7f;
    const float e8  =  2.48015873015873016e-5f;
    const float e6  = -1.38888888888888889e-3f;
    const float c4  =  0.041666667908430099487304688f;

    float F  = fmaf(r2h, e10, e8);
    F        = fmaf(r2h, F, e6);
    float Eh = fmaf(r2h, F, c4);                   // E(r^2)
    float r4h = r2h * r2h;
    float Ah  = 1.0f - hh;
    float Al  = (1.0f - Ah) - hh;                  // exact Fast2Sum
    float ctail = fmaf(r4h, Eh, Al);
    ctail = fmaf(-0.5f, r2l, ctail);
    ctail = fmaf(-rhi, rlo, ctail);
    float cosr = Ah + ctail;

    // ---- quadrant fixup ----
    int m = n & 3;
    float s = (m & 1) ? cosr : sinr;
    float c = (m & 1) ? sinr : cosr;
    if (m & 2)       s = -s;
    if ((m + 1) & 2) c = -c;
    s_out = s;
    c_out = c;
}

// ---------------------------------------------------------------------------
// Per-point distance from smem-staged data. KEY IDENTITY: the reference's ENU
// basis is an orthonormal rotation of d = pred - ref, so |ENU| == |d| up to
// f32 rounding of the rotation itself (~2^-22 RELATIVE on an O(3.5 m) value,
// NOT amplified by the 6.4e6 m geometry). The 9-FMA rotation is dropped.
__device__ __forceinline__ float dist_s(const float* __restrict__ sp,
                                        const float* __restrict__ st) {
    const float DEG2RAD = 0.017453292519943295f;
    const float E2      = 0.00669437999014f;
    const float A       = 6378137.0f;
    const float C1mE2   = 0.99330562000986f;

    float lat = st[0], lon = st[1], h = st[2];

    float latr = __fmul_rn(lat, DEG2RAD);
    float lonr = __fmul_rn(lon, DEG2RAD);

    float sl, cl, so, co;
    lean_sincos(latr, sl, cl);
    lean_sincos(lonr, so, co);

    // t = 1 - ((E2*sl)*sl)  (exact reference association)
    float t = __fsub_rn(1.0f, __fmul_rn(__fmul_rn(E2, sl), sl));

    // s = rn(sqrt(t)) via rsqrt + exact-residual Newton (mismatch p ~ 2^-18)
    float y0 = rsqrt_ap(t);
    float s0 = __fmul_rn(t, y0);
    float es = __fmaf_rn(s0, s0, -t);
    float hlf = __fmul_rn(0.5f, y0);
    float s  = __fmaf_rn(es, -hlf, s0);

    // N = rn(A / s) via rcp + exact-residual Newton (mismatch p ~ 2^-18)
    float r0 = rcp_ap(s);
    float q0 = __fmul_rn(A, r0);
    float eq = __fmaf_rn(q0, s, -A);
    float N  = __fmaf_rn(eq, -r0, q0);

    float Nh = __fadd_rn(N, h);
    float Nhcl = __fmul_rn(Nh, cl);
    float rx = __fmul_rn(Nhcl, co);
    float ry = __fmul_rn(Nhcl, so);
    float rz = __fmul_rn(__fadd_rn(__fmul_rn(N, C1mE2), h), sl);

    float dx = __fsub_rn(sp[0], rx);
    float dy = __fsub_rn(sp[1], ry);
    float dz = __fsub_rn(sp[2], rz);

    float d2 = fmaf(dx, dx, fmaf(dy, dy, dz * dz));
    return sqrt_ap(d2);
}

// ---------------------------------------------------------------------------
// Fused persistent kernel: cp.async double-buffered staging of BOTH arrays,
// 2 points/thread/tile, grid barrier, focal sum, deterministic finish.
__global__ void __launch_bounds__(NTHREADS, 4)
k_fused(const float* __restrict__ inp, const float* __restrict__ tgt,
        float* __restrict__ out, int B) {
    __shared__ float s_dist[CHUNK];
    __shared__ float s_tgt[2][TILE * 3];
    __shared__ float s_inp[2][TILE * 3];
    __shared__ float s_red[NTHREADS / 32];

    int start = blockIdx.x * CHUNK;
    int cnt   = min(CHUNK, B - start);
    if (cnt < 0) cnt = 0;
    int ntiles = (cnt + TILE - 1) / TILE;

    int lane = threadIdx.x & 31, wid = threadIdx.x >> 5;

    // ---------------- Phase 1: pipelined distances -> smem ----------------
    if (ntiles > 0) {
        int pc  = min(TILE, cnt);
        int nf4 = (pc * 3) >> 2;                    // pc multiple of 4
        const float* gt = tgt + 3 * start;
        const float* gi = inp + 3 * start;
        for (int i = threadIdx.x; i < nf4; i += NTHREADS) {
            cp16(&s_tgt[0][i * 4], gt + i * 4);
            cp16(&s_inp[0][i * 4], gi + i * 4);
        }
    }
    asm volatile("cp.async.commit_group;");

    float local_max = 0.0f;
    for (int t = 0; t < ntiles; t++) {
        if (t + 1 < ntiles) {
            int p0  = (t + 1) * TILE;
            int pc  = min(TILE, cnt - p0);
            int nf4 = (pc * 3) >> 2;
            int bs  = (t + 1) & 1;
            const float* gt = tgt + 3 * (start + p0);
            const float* gi = inp + 3 * (start + p0);
            for (int i = threadIdx.x; i < nf4; i += NTHREADS) {
                cp16(&s_tgt[bs][i * 4], gt + i * 4);
                cp16(&s_inp[bs][i * 4], gi + i * 4);
            }
            asm volatile("cp.async.commit_group;");
            asm volatile("cp.async.wait_group 1;");
        } else {
            asm volatile("cp.async.wait_group 0;");
        }
        __syncthreads();                            // tile t visible to all

        int b  = t & 1;
        int k0 = t * TILE + threadIdx.x;            // point 0
        int k1 = k0 + NTHREADS;                     // point 1 (independent)
        if (k0 < cnt) {
            int j = threadIdx.x * 3;
            float d = dist_s(&s_inp[b][j], &s_tgt[b][j]);
            s_dist[k0] = d;
            local_max = fmaxf(local_max, d);
        }
        if (k1 < cnt) {
            int j = (threadIdx.x + NTHREADS) * 3;
            float d = dist_s(&s_inp[b][j], &s_tgt[b][j]);
            s_dist[k1] = d;
            local_max = fmaxf(local_max, d);
        }
        __syncthreads();                            // done reading buf before t+2 stage
    }

    #pragma unroll
    for (int o = 16; o > 0; o >>= 1)
        local_max = fmaxf(local_max, __shfl_xor_sync(0xFFFFFFFFu, local_max, o));
    if (lane == 0) s_red[wid] = local_max;
    __syncthreads();
    if (wid == 0) {
        float v = (lane < NTHREADS / 32) ? s_red[lane] : 0.0f;
        #pragma unroll
        for (int o = 16; o > 0; o >>= 1)
            v = fmaxf(v, __shfl_xor_sync(0xFFFFFFFFu, v, o));
        if (lane == 0) g_blockmax[blockIdx.x] = v;
    }

    // ---------------- Grid barrier (flag-flip, replay-safe) ----------------
    __threadfence();
    if (threadIdx.x == 0) {
        unsigned f = g_bar_flag;
        unsigned arrived = atomicAdd(&g_bar_count, 1u);
        if (arrived == BLOCKS - 1) {
            g_bar_count = 0;
            __threadfence();
            g_bar_flag = f ^ 1u;
        } else {
            while (g_bar_flag == f) { }
        }
    }
    __syncthreads();
    __threadfence();

    // ---------------- Global max (every block, fixed order) ----------------
    float m = 0.0f;
    for (int i = threadIdx.x; i < BLOCKS; i += NTHREADS)
        m = fmaxf(m, g_blockmax[i]);
    #pragma unroll
    for (int o = 16; o > 0; o >>= 1)
        m = fmaxf(m, __shfl_xor_sync(0xFFFFFFFFu, m, o));
    if (lane == 0) s_red[wid] = m;
    __syncthreads();
    if (wid == 0) {
        float v = (lane < NTHREADS / 32) ? s_red[lane] : 0.0f;
        #pragma unroll
        for (int o = 16; o > 0; o >>= 1)
            v = fmaxf(v, __shfl_xor_sync(0xFFFFFFFFu, v, o));
        if (lane == 0) s_red[0] = v;
    }
    __syncthreads();
    float inv_denom = 1.0f / __fadd_rn(s_red[0], 1e-8f);
    __syncthreads();

    // ---------------- Phase 2: focal loss^2 from smem ----------------
    // fl^2 = d^2 * base^(2g), 2g = 4*exp(-d) = ex2(2 - d*log2(e))
    const float L2E = 1.4426950408889634f;          // log2(e)
    float sum = 0.0f;
    for (int i = threadIdx.x; i < cnt; i += NTHREADS) {
        float d    = s_dist[i];
        float G    = ex2_ap(fmaf(-L2E, d, 2.0f));   // 2*gamma = 4*exp(-d)
        float base = 1.0f - sqrt_ap(d * inv_denom);
        float w2   = ex2_ap(G * lg2_ap(base));      // base^(2g)
        sum = fmaf(w2, d * d, sum);
    }

    #pragma unroll
    for (int o = 16; o > 0; o >>= 1)
        sum += __shfl_xor_sync(0xFFFFFFFFu, sum, o);
    if (lane == 0) s_red[wid] = sum;
    __syncthreads();
    if (wid == 0) {
        float v = (lane < NTHREADS / 32) ? s_red[lane] : 0.0f;
        #pragma unroll
        for (int o = 16; o > 0; o >>= 1)
            v += __shfl_xor_sync(0xFFFFFFFFu, v, o);
        if (lane == 0) g_partials[blockIdx.x] = v;
    }

    // ---------------- Last block finishes (deterministic) ----------------
    __shared__ unsigned s_ticket;
    __threadfence();
    if (threadIdx.x == 0)
        s_ticket = atomicAdd(&g_ticket, 1u);
    __syncthreads();
    if (s_ticket == BLOCKS - 1) {
        __threadfence();
        float fs = 0.0f;
        for (int i = threadIdx.x; i < BLOCKS; i += NTHREADS)
            fs += g_partials[i];
        #pragma unroll
        for (int o = 16; o > 0; o >>= 1)
            fs += __shfl_xor_sync(0xFFFFFFFFu, fs, o);
        __syncthreads();
        if (lane == 0) s_red[wid] = fs;
        __syncthreads();
        if (wid == 0) {
            float v = (lane < NTHREADS / 32) ? s_red[lane] : 0.0f;
            #pragma unroll
            for (int o = 16; o > 0; o >>= 1)
                v += __shfl_xor_sync(0xFFFFFFFFu, v, o);
            if (lane == 0) {
                out[0] = sqrtf(v / (float)B);
                g_ticket = 0;
            }
        }
    }
}

// ---------------------------------------------------------------------------
extern "C" void kernel_launch(void* const* d_in, const int* in_sizes, int n_in,
                              void* d_out, int out_size) {
    const float* inp = (const float*)d_in[0];   // (B,3) pred ECEF
    const float* tgt = (const float*)d_in[1];   // (B,3) lat/lon/h
    int B = in_sizes[0] / 3;
    float* out = (float*)d_out;

    k_fused<<<BLOCKS, NTHREADS>>>(inp, tgt, out, B);
}

// round 16
// speedup vs baseline: 1.1712x; 1.0068x over previous
#include <cuda_runtime.h>
#include <math.h>

#define B_MAX    4000000
#define BLOCKS   592        // 148 SMs * 4, all co-resident (required for barrier)
#define NTHREADS 256
#define CHUNK    6784       // multiple of 4 -> 16B staging alignment; 592*6784 >= 4M
#define TILE     512        // 2 points per thread per tile

__device__ float             g_blockmax[BLOCKS];
__device__ float             g_partials[BLOCKS];
__device__ unsigned int      g_bar_count = 0;
__device__ volatile unsigned g_bar_flag  = 0;
__device__ unsigned int      g_ticket    = 0;

// ---------------------------------------------------------------------------
__device__ __forceinline__ float rsqrt_ap(float x) {
    float y; asm("rsqrt.approx.f32 %0, %1;" : "=f"(y) : "f"(x)); return y;
}
__device__ __forceinline__ float rcp_ap(float x) {
    float y; asm("rcp.approx.f32 %0, %1;" : "=f"(y) : "f"(x)); return y;
}
__device__ __forceinline__ float sqrt_ap(float x) {
    float y; asm("sqrt.approx.f32 %0, %1;" : "=f"(y) : "f"(x)); return y;
}
__device__ __forceinline__ float ex2_ap(float x) {
    float y; asm("ex2.approx.f32 %0, %1;" : "=f"(y) : "f"(x)); return y;
}
__device__ __forceinline__ float lg2_ap(float x) {
    float y; asm("lg2.approx.f32 %0, %1;" : "=f"(y) : "f"(x)); return y;
}
__device__ __forceinline__ void cp16(void* sdst, const void* gsrc) {
    unsigned saddr = (unsigned)__cvta_generic_to_shared(sdst);
    asm volatile("cp.async.ca.shared.global [%0], [%1], 16;" :: "r"(saddr), "l"(gsrc));
}

// ---------------------------------------------------------------------------
// Lean compensated sincos for |x| <= pi+eps. Abs error ~2^-26.5 (sin) /
// 2^-27.8 (cos) — calibrated: costs ~0.8e-4 of rel_err vs correctly-rounded.
__device__ __forceinline__ void lean_sincos(float x, float& s_out, float& c_out) {
    const float TWO_OVER_PI = 0.63661977236758134f;
    const float C1 = 1.57079637050628662109375f;   // float(pi/2)
    const float C2 = -4.37113900018624283e-8f;     // pi/2 - C1 (rounded)

    float qf = rintf(x * TWO_OVER_PI);             // q in {-2..2}
    int   n  = (int)qf;

    float a   = fmaf(qf, -C1, x);                  // exact
    float b   = -qf * C2;
    float rhi = a + b;
    float t0  = rhi - a;
    float rlo = b - t0;                            // Fast2Sum low word

    float r2h = rhi * rhi;
    float r2l = fmaf(rhi, rhi, -r2h);              // exact low part of rhi^2

    // ---- sin(rhi) + rlo*cos(rhi) ----
    const float c11 = -2.50521083854417202e-8f;
    const float c9  =  2.75573192239858907e-6f;
    const float c7  = -1.98412698412698413e-4f;
    const float c5  =  8.33333333333333333e-3f;
    const float c3  = -0.16666667163372039794921875f;

    float U  = fmaf(r2h, c11, c9);
    U        = fmaf(r2h, U, c7);
    U        = fmaf(r2h, U, c5);
    float vh = fmaf(r2h, U, c3);                   // V(r^2)
    float wh = r2h * rhi;                          // r^3
    float hh = 0.5f * r2h;                         // exact
    float rloc = fmaf(-hh, rlo, rlo);              // rlo*cos(rhi) approx
    float stail = fmaf(wh, vh, rloc);
    float sinr  = rhi + stail;

    // ---- cos(rhi) - rhi*rlo ----
    const float e10 = -2.75573192239858907e-7f;
    const float e8  =  2.48015873015873016e-5f;
    const float e6  = -1.38888888888888889e-3f;
    const float c4  =  0.041666667908430099487304688f;

    float F  = fmaf(r2h, e10, e8);
    F        = fmaf(r2h, F, e6);
    float Eh = fmaf(r2h, F, c4);                   // E(r^2)
    float r4h = r2h * r2h;
    float Ah  = 1.0f - hh;
    float Al  = (1.0f - Ah) - hh;                  // exact Fast2Sum
    float ctail = fmaf(r4h, Eh, Al);
    ctail = fmaf(-0.5f, r2l, ctail);
    ctail = fmaf(-rhi, rlo, ctail);
    float cosr = Ah + ctail;

    // ---- quadrant fixup ----
    int m = n & 3;
    float s = (m & 1) ? cosr : sinr;
    float c = (m & 1) ? sinr : cosr;
    if (m & 2)       s = -s;
    if ((m + 1) & 2) c = -c;
    s_out = s;
    c_out = c;
}

// ---------------------------------------------------------------------------
// Per-point distance from smem-staged data. The reference's ENU basis is an
// orthonormal rotation of d = pred - ref, so |ENU| == |d| up to unamplified
// f32 rounding of the rotation; the 9-FMA rotation is dropped.
__device__ __forceinline__ float dist_s(const float* __restrict__ sp,
                                        const float* __restrict__ st) {
    const float DEG2RAD = 0.017453292519943295f;
    const float E2      = 0.00669437999014f;
    const float A       = 6378137.0f;
    const float C1mE2   = 0.99330562000986f;

    float lat = st[0], lon = st[1], h = st[2];

    float latr = __fmul_rn(lat, DEG2RAD);
    float lonr = __fmul_rn(lon, DEG2RAD);

    float sl, cl, so, co;
    lean_sincos(latr, sl, cl);
    lean_sincos(lonr, so, co);

    // t = 1 - ((E2*sl)*sl)  (exact reference association)
    float t = __fsub_rn(1.0f, __fmul_rn(__fmul_rn(E2, sl), sl));

    // s = rn(sqrt(t)) via rsqrt + exact-residual Newton (mismatch p ~ 2^-18)
    float y0 = rsqrt_ap(t);
    float s0 = __fmul_rn(t, y0);
    float es = __fmaf_rn(s0, s0, -t);
    float hlf = __fmul_rn(0.5f, y0);
    float s  = __fmaf_rn(es, -hlf, s0);

    // N = rn(A / s) via rcp + exact-residual Newton (mismatch p ~ 2^-18)
    float r0 = rcp_ap(s);
    float q0 = __fmul_rn(A, r0);
    float eq = __fmaf_rn(q0, s, -A);
    float N  = __fmaf_rn(eq, -r0, q0);

    float Nh = __fadd_rn(N, h);
    float Nhcl = __fmul_rn(Nh, cl);
    float rx = __fmul_rn(Nhcl, co);
    float ry = __fmul_rn(Nhcl, so);
    float rz = __fmul_rn(__fadd_rn(__fmul_rn(N, C1mE2), h), sl);

    float dx = __fsub_rn(sp[0], rx);
    float dy = __fsub_rn(sp[1], ry);
    float dz = __fsub_rn(sp[2], rz);

    float d2 = fmaf(dx, dx, fmaf(dy, dy, dz * dz));
    return sqrt_ap(d2);
}

// ---------------------------------------------------------------------------
// Fused persistent kernel: cp.async double-buffered staging of BOTH arrays,
// 2 points/thread/tile in ONE basic block (cross-point ILP), grid barrier,
// 2-way-unrolled focal sum, deterministic last-block finish.
__global__ void __launch_bounds__(NTHREADS, 4)
k_fused(const float* __restrict__ inp, const float* __restrict__ tgt,
        float* __restrict__ out, int B) {
    __shared__ float s_dist[CHUNK];
    __shared__ float s_tgt[2][TILE * 3];
    __shared__ float s_inp[2][TILE * 3];
    __shared__ float s_red[NTHREADS / 32];

    int start = blockIdx.x * CHUNK;
    int cnt   = min(CHUNK, B - start);
    if (cnt < 0) cnt = 0;
    int ntiles = (cnt + TILE - 1) / TILE;

    int lane = threadIdx.x & 31, wid = threadIdx.x >> 5;

    // ---------------- Phase 1: pipelined distances -> smem ----------------
    if (ntiles > 0) {
        int pc  = min(TILE, cnt);
        int nf4 = (pc * 3) >> 2;                    // pc multiple of 4
        const float* gt = tgt + 3 * start;
        const float* gi = inp + 3 * start;
        for (int i = threadIdx.x; i < nf4; i += NTHREADS) {
            cp16(&s_tgt[0][i * 4], gt + i * 4);
            cp16(&s_inp[0][i * 4], gi + i * 4);
        }
    }
    asm volatile("cp.async.commit_group;");

    float local_max = 0.0f;
    for (int t = 0; t < ntiles; t++) {
        if (t + 1 < ntiles) {
            int p0  = (t + 1) * TILE;
            int pc  = min(TILE, cnt - p0);
            int nf4 = (pc * 3) >> 2;
            int bs  = (t + 1) & 1;
            const float* gt = tgt + 3 * (start + p0);
            const float* gi = inp + 3 * (start + p0);
            for (int i = threadIdx.x; i < nf4; i += NTHREADS) {
                cp16(&s_tgt[bs][i * 4], gt + i * 4);
                cp16(&s_inp[bs][i * 4], gi + i * 4);
            }
            asm volatile("cp.async.commit_group;");
            asm volatile("cp.async.wait_group 1;");
        } else {
            asm volatile("cp.async.wait_group 0;");
        }
        __syncthreads();                            // tile t visible to all

        int b  = t & 1;
        int k0 = t * TILE + threadIdx.x;            // point 0
        int k1 = k0 + NTHREADS;                     // point 1 (independent)
        int j0 = threadIdx.x * 3;
        int j1 = (threadIdx.x + NTHREADS) * 3;
        if (k1 < cnt) {
            // fast path: BOTH points in one basic block -> ptxas interleaves
            // the two independent ~100-op dependency chains (2x ILP)
            float d0 = dist_s(&s_inp[b][j0], &s_tgt[b][j0]);
            float d1 = dist_s(&s_inp[b][j1], &s_tgt[b][j1]);
            s_dist[k0] = d0;
            s_dist[k1] = d1;
            local_max = fmaxf(local_max, fmaxf(d0, d1));
        } else if (k0 < cnt) {
            float d0 = dist_s(&s_inp[b][j0], &s_tgt[b][j0]);
            s_dist[k0] = d0;
            local_max = fmaxf(local_max, d0);
        }
        __syncthreads();                            // done reading buf before t+2 stage
    }

    #pragma unroll
    for (int o = 16; o > 0; o >>= 1)
        local_max = fmaxf(local_max, __shfl_xor_sync(0xFFFFFFFFu, local_max, o));
    if (lane == 0) s_red[wid] = local_max;
    __syncthreads();
    if (wid == 0) {
        float v = (lane < NTHREADS / 32) ? s_red[lane] : 0.0f;
        #pragma unroll
        for (int o = 16; o > 0; o >>= 1)
            v = fmaxf(v, __shfl_xor_sync(0xFFFFFFFFu, v, o));
        if (lane == 0) g_blockmax[blockIdx.x] = v;
    }

    // ---------------- Grid barrier (flag-flip, replay-safe) ----------------
    __threadfence();
    if (threadIdx.x == 0) {
        unsigned f = g_bar_flag;
        unsigned arrived = atomicAdd(&g_bar_count, 1u);
        if (arrived == BLOCKS - 1) {
            g_bar_count = 0;
            __threadfence();
            g_bar_flag = f ^ 1u;
        } else {
            while (g_bar_flag == f) { }
        }
    }
    __syncthreads();
    __threadfence();

    // ---------------- Global max (every block, fixed order) ----------------
    float m = 0.0f;
    for (int i = threadIdx.x; i < BLOCKS; i += NTHREADS)
        m = fmaxf(m, g_blockmax[i]);
    #pragma unroll
    for (int o = 16; o > 0; o >>= 1)
        m = fmaxf(m, __shfl_xor_sync(0xFFFFFFFFu, m, o));
    if (lane == 0) s_red[wid] = m;
    __syncthreads();
    if (wid == 0) {
        float v = (lane < NTHREADS / 32) ? s_red[lane] : 0.0f;
        #pragma unroll
        for (int o = 16; o > 0; o >>= 1)
            v = fmaxf(v, __shfl_xor_sync(0xFFFFFFFFu, v, o));
        if (lane == 0) s_red[0] = v;
    }
    __syncthreads();
    float inv_denom = 1.0f / __fadd_rn(s_red[0], 1e-8f);
    __syncthreads();

    // ---------------- Phase 2: focal loss^2 from smem (2-way ILP) ----------
    // fl^2 = d^2 * base^(2g), 2g = 4*exp(-d) = ex2(2 - d*log2(e))
    const float L2E = 1.4426950408889634f;          // log2(e)
    float sum = 0.0f;
    int i = threadIdx.x;
    for (; i + NTHREADS < cnt; i += 2 * NTHREADS) {
        float da = s_dist[i];
        float db = s_dist[i + NTHREADS];
        float Ga = ex2_ap(fmaf(-L2E, da, 2.0f));
        float Gb = ex2_ap(fmaf(-L2E, db, 2.0f));
        float ba = 1.0f - sqrt_ap(da * inv_denom);
        float bb = 1.0f - sqrt_ap(db * inv_denom);
        float wa = ex2_ap(Ga * lg2_ap(ba));
        float wb = ex2_ap(Gb * lg2_ap(bb));
        sum = fmaf(wa, da * da, sum);
        sum = fmaf(wb, db * db, sum);
    }
    if (i < cnt) {
        float d    = s_dist[i];
        float G    = ex2_ap(fmaf(-L2E, d, 2.0f));
        float base = 1.0f - sqrt_ap(d * inv_denom);
        float w2   = ex2_ap(G * lg2_ap(base));
        sum = fmaf(w2, d * d, sum);
    }

    #pragma unroll
    for (int o = 16; o > 0; o >>= 1)
        sum += __shfl_xor_sync(0xFFFFFFFFu, sum, o);
    if (lane == 0) s_red[wid] = sum;
    __syncthreads();
    if (wid == 0) {
        float v = (lane < NTHREADS / 32) ? s_red[lane] : 0.0f;
        #pragma unroll
        for (int o = 16; o > 0; o >>= 1)
            v += __shfl_xor_sync(0xFFFFFFFFu, v, o);
        if (lane == 0) g_partials[blockIdx.x] = v;
    }

    // ---------------- Last block finishes (deterministic) ----------------
    __shared__ unsigned s_ticket;
    __threadfence();
    if (threadIdx.x == 0)
        s_ticket = atomicAdd(&g_ticket, 1u);
    __syncthreads();
    if (s_ticket == BLOCKS - 1) {
        __threadfence();
        float fs = 0.0f;
        for (int k = threadIdx.x; k < BLOCKS; k += NTHREADS)
            fs += g_partials[k];
        #pragma unroll
        for (int o = 16; o > 0; o >>= 1)
            fs += __shfl_xor_sync(0xFFFFFFFFu, fs, o);
        __syncthreads();
        if (lane == 0) s_red[wid] = fs;
        __syncthreads();
        if (wid == 0) {
            float v = (lane < NTHREADS / 32) ? s_red[lane] : 0.0f;
            #pragma unroll
            for (int o = 16; o > 0; o >>= 1)
                v += __shfl_xor_sync(0xFFFFFFFFu, v, o);
            if (lane == 0) {
                out[0] = sqrtf(v / (float)B);
                g_ticket = 0;
            }
        }
    }
}

// ---------------------------------------------------------------------------
extern "C" void kernel_launch(void* const* d_in, const int* in_sizes, int n_in,
                              void* d_out, int out_size) {
    const float* inp = (const float*)d_in[0];   // (B,3) pred ECEF
    const float* tgt = (const float*)d_in[1];   // (B,3) lat/lon/h
    int B = in_sizes[0] / 3;
    float* out = (float*)d_out;

    k_fused<<<BLOCKS, NTHREADS>>>(inp, tgt, out, B);
}

// round 17
// speedup vs baseline: 1.2313x; 1.0513x over previous
#include <cuda_runtime.h>
#include <math.h>

#define B_MAX    4000000
#define BLOCKS   592        // 148 SMs * 4, all co-resident (required for barrier)
#define NTHREADS 128        // 4 points/thread/tile -> 4-way ILP, 128 regs/thread budget
#define CHUNK    6784       // multiple of 4 -> 16B staging alignment; 592*6784 >= 4M
#define TILE     512        // 4 points per thread per tile

__device__ float             g_blockmax[BLOCKS];
__device__ float             g_partials[BLOCKS];
__device__ unsigned int      g_bar_count = 0;
__device__ volatile unsigned g_bar_flag  = 0;
__device__ unsigned int      g_ticket    = 0;

// ---------------------------------------------------------------------------
__device__ __forceinline__ float rsqrt_ap(float x) {
    float y; asm("rsqrt.approx.f32 %0, %1;" : "=f"(y) : "f"(x)); return y;
}
__device__ __forceinline__ float rcp_ap(float x) {
    float y; asm("rcp.approx.f32 %0, %1;" : "=f"(y) : "f"(x)); return y;
}
__device__ __forceinline__ float sqrt_ap(float x) {
    float y; asm("sqrt.approx.f32 %0, %1;" : "=f"(y) : "f"(x)); return y;
}
__device__ __forceinline__ float ex2_ap(float x) {
    float y; asm("ex2.approx.f32 %0, %1;" : "=f"(y) : "f"(x)); return y;
}
__device__ __forceinline__ float lg2_ap(float x) {
    float y; asm("lg2.approx.f32 %0, %1;" : "=f"(y) : "f"(x)); return y;
}
__device__ __forceinline__ void cp16(void* sdst, const void* gsrc) {
    unsigned saddr = (unsigned)__cvta_generic_to_shared(sdst);
    asm volatile("cp.async.ca.shared.global [%0], [%1], 16;" :: "r"(saddr), "l"(gsrc));
}

// ---------------------------------------------------------------------------
// Lean compensated sincos for |x| <= pi+eps. Abs error ~2^-26.5 (sin) /
// 2^-27.8 (cos) — calibrated: costs ~2e-4 of rel_err vs correctly-rounded.
__device__ __forceinline__ void lean_sincos(float x, float& s_out, float& c_out) {
    const float TWO_OVER_PI = 0.63661977236758134f;
    const float C1 = 1.57079637050628662109375f;   // float(pi/2)
    const float C2 = -4.37113900018624283e-8f;     // pi/2 - C1 (rounded)

    float qf = rintf(x * TWO_OVER_PI);             // q in {-2..2}
    int   n  = (int)qf;

    float a   = fmaf(qf, -C1, x);                  // exact
    float b   = -qf * C2;
    float rhi = a + b;
    float t0  = rhi - a;
    float rlo = b - t0;                            // Fast2Sum low word

    float r2h = rhi * rhi;
    float r2l = fmaf(rhi, rhi, -r2h);              // exact low part of rhi^2

    // ---- sin(rhi) + rlo*cos(rhi) ----
    const float c11 = -2.50521083854417202e-8f;
    const float c9  =  2.75573192239858907e-6f;
    const float c7  = -1.98412698412698413e-4f;
    const float c5  =  8.33333333333333333e-3f;
    const float c3  = -0.16666667163372039794921875f;

    float U  = fmaf(r2h, c11, c9);
    U        = fmaf(r2h, U, c7);
    U        = fmaf(r2h, U, c5);
    float vh = fmaf(r2h, U, c3);                   // V(r^2)
    float wh = r2h * rhi;                          // r^3
    float hh = 0.5f * r2h;                         // exact
    float rloc = fmaf(-hh, rlo, rlo);              // rlo*cos(rhi) approx
    float stail = fmaf(wh, vh, rloc);
    float sinr  = rhi + stail;

    // ---- cos(rhi) - rhi*rlo ----
    const float e10 = -2.75573192239858907e-7f;
    const float e8  =  2.48015873015873016e-5f;
    const float e6  = -1.38888888888888889e-3f;
    const float c4  =  0.041666667908430099487304688f;

    float F  = fmaf(r2h, e10, e8);
    F        = fmaf(r2h, F, e6);
    float Eh = fmaf(r2h, F, c4);                   // E(r^2)
    float r4h = r2h * r2h;
    float Ah  = 1.0f - hh;
    float Al  = (1.0f - Ah) - hh;                  // exact Fast2Sum
    float ctail = fmaf(r4h, Eh, Al);
    ctail = fmaf(-0.5f, r2l, ctail);
    ctail = fmaf(-rhi, rlo, ctail);
    float cosr = Ah + ctail;

    // ---- quadrant fixup ----
    int m = n & 3;
    float s = (m & 1) ? cosr : sinr;
    float c = (m & 1) ? sinr : cosr;
    if (m & 2)       s = -s;
    if ((m + 1) & 2) c = -c;
    s_out = s;
    c_out = c;
}

// ---------------------------------------------------------------------------
// Per-point distance from smem-staged data. The reference's ENU basis is an
// orthonormal rotation of d = pred - ref, so |ENU| == |d| up to unamplified
// f32 rounding of the rotation; the 9-FMA rotation is dropped.
__device__ __forceinline__ float dist_s(const float* __restrict__ sp,
                                        const float* __restrict__ st) {
    const float DEG2RAD = 0.017453292519943295f;
    const float E2      = 0.00669437999014f;
    const float A       = 6378137.0f;
    const float C1mE2   = 0.99330562000986f;

    float lat = st[0], lon = st[1], h = st[2];

    float latr = __fmul_rn(lat, DEG2RAD);
    float lonr = __fmul_rn(lon, DEG2RAD);

    float sl, cl, so, co;
    lean_sincos(latr, sl, cl);
    lean_sincos(lonr, so, co);

    // t = 1 - ((E2*sl)*sl)  (exact reference association)
    float t = __fsub_rn(1.0f, __fmul_rn(__fmul_rn(E2, sl), sl));

    // s = rn(sqrt(t)) via rsqrt + exact-residual Newton (mismatch p ~ 2^-18)
    float y0 = rsqrt_ap(t);
    float s0 = __fmul_rn(t, y0);
    float es = __fmaf_rn(s0, s0, -t);
    float hlf = __fmul_rn(0.5f, y0);
    float s  = __fmaf_rn(es, -hlf, s0);

    // N = rn(A / s) via rcp + exact-residual Newton (mismatch p ~ 2^-18)
    float r0 = rcp_ap(s);
    float q0 = __fmul_rn(A, r0);
    float eq = __fmaf_rn(q0, s, -A);
    float N  = __fmaf_rn(eq, -r0, q0);

    float Nh = __fadd_rn(N, h);
    float Nhcl = __fmul_rn(Nh, cl);
    float rx = __fmul_rn(Nhcl, co);
    float ry = __fmul_rn(Nhcl, so);
    float rz = __fmul_rn(__fadd_rn(__fmul_rn(N, C1mE2), h), sl);

    float dx = __fsub_rn(sp[0], rx);
    float dy = __fsub_rn(sp[1], ry);
    float dz = __fsub_rn(sp[2], rz);

    float d2 = fmaf(dx, dx, fmaf(dy, dy, dz * dz));
    return sqrt_ap(d2);
}

// ---------------------------------------------------------------------------
// Fused persistent kernel: cp.async double-buffered staging of BOTH arrays,
// 4 points/thread/tile in ONE basic block (4-way ILP), grid barrier,
// 2-way-unrolled focal sum, deterministic last-block finish.
__global__ void __launch_bounds__(NTHREADS, 4)
k_fused(const float* __restrict__ inp, const float* __restrict__ tgt,
        float* __restrict__ out, int B) {
    __shared__ float s_dist[CHUNK];
    __shared__ float s_tgt[2][TILE * 3];
    __shared__ float s_inp[2][TILE * 3];
    __shared__ float s_red[NTHREADS / 32];

    int start = blockIdx.x * CHUNK;
    int cnt   = min(CHUNK, B - start);
    if (cnt < 0) cnt = 0;
    int ntiles = (cnt + TILE - 1) / TILE;

    int lane = threadIdx.x & 31, wid = threadIdx.x >> 5;

    // ---------------- Phase 1: pipelined distances -> smem ----------------
    if (ntiles > 0) {
        int pc  = min(TILE, cnt);
        int nf4 = (pc * 3) >> 2;                    // pc multiple of 4
        const float* gt = tgt + 3 * start;
        const float* gi = inp + 3 * start;
        for (int i = threadIdx.x; i < nf4; i += NTHREADS) {
            cp16(&s_tgt[0][i * 4], gt + i * 4);
            cp16(&s_inp[0][i * 4], gi + i * 4);
        }
    }
    asm volatile("cp.async.commit_group;");

    float local_max = 0.0f;
    for (int t = 0; t < ntiles; t++) {
        if (t + 1 < ntiles) {
            int p0  = (t + 1) * TILE;
            int pc  = min(TILE, cnt - p0);
            int nf4 = (pc * 3) >> 2;
            int bs  = (t + 1) & 1;
            const float* gt = tgt + 3 * (start + p0);
            const float* gi = inp + 3 * (start + p0);
            for (int i = threadIdx.x; i < nf4; i += NTHREADS) {
                cp16(&s_tgt[bs][i * 4], gt + i * 4);
                cp16(&s_inp[bs][i * 4], gi + i * 4);
            }
            asm volatile("cp.async.commit_group;");
            asm volatile("cp.async.wait_group 1;");
        } else {
            asm volatile("cp.async.wait_group 0;");
        }
        __syncthreads();                            // tile t visible to all

        int b  = t & 1;
        int k0 = t * TILE + threadIdx.x;
        int j0 = threadIdx.x * 3;
        if (t * TILE + TILE <= cnt) {
            // fast path: FOUR independent ~100-op chains in one basic block
            float d0 = dist_s(&s_inp[b][j0],                  &s_tgt[b][j0]);
            float d1 = dist_s(&s_inp[b][j0 + 3 * NTHREADS],   &s_tgt[b][j0 + 3 * NTHREADS]);
            float d2 = dist_s(&s_inp[b][j0 + 6 * NTHREADS],   &s_tgt[b][j0 + 6 * NTHREADS]);
            float d3 = dist_s(&s_inp[b][j0 + 9 * NTHREADS],   &s_tgt[b][j0 + 9 * NTHREADS]);
            s_dist[k0]                = d0;
            s_dist[k0 + NTHREADS]     = d1;
            s_dist[k0 + 2 * NTHREADS] = d2;
            s_dist[k0 + 3 * NTHREADS] = d3;
            local_max = fmaxf(local_max, fmaxf(fmaxf(d0, d1), fmaxf(d2, d3)));
        } else {
            #pragma unroll
            for (int p = 0; p < 4; p++) {
                int k = k0 + p * NTHREADS;
                if (k < cnt) {
                    int j = j0 + p * 3 * NTHREADS;
                    float d = dist_s(&s_inp[b][j], &s_tgt[b][j]);
                    s_dist[k] = d;
                    local_max = fmaxf(local_max, d);
                }
            }
        }
        __syncthreads();                            // done reading buf before t+2 stage
    }

    #pragma unroll
    for (int o = 16; o > 0; o >>= 1)
        local_max = fmaxf(local_max, __shfl_xor_sync(0xFFFFFFFFu, local_max, o));
    if (lane == 0) s_red[wid] = local_max;
    __syncthreads();
    if (wid == 0) {
        float v = (lane < NTHREADS / 32) ? s_red[lane] : 0.0f;
        #pragma unroll
        for (int o = 16; o > 0; o >>= 1)
            v = fmaxf(v, __shfl_xor_sync(0xFFFFFFFFu, v, o));
        if (lane == 0) g_blockmax[blockIdx.x] = v;
    }

    // ---------------- Grid barrier (flag-flip, replay-safe) ----------------
    __threadfence();
    if (threadIdx.x == 0) {
        unsigned f = g_bar_flag;
        unsigned arrived = atomicAdd(&g_bar_count, 1u);
        if (arrived == BLOCKS - 1) {
            g_bar_count = 0;
            __threadfence();
            g_bar_flag = f ^ 1u;
        } else {
            while (g_bar_flag == f) { }
        }
    }
    __syncthreads();
    __threadfence();

    // ---------------- Global max (every block, fixed order) ----------------
    float m = 0.0f;
    for (int i = threadIdx.x; i < BLOCKS; i += NTHREADS)
        m = fmaxf(m, g_blockmax[i]);
    #pragma unroll
    for (int o = 16; o > 0; o >>= 1)
        m = fmaxf(m, __shfl_xor_sync(0xFFFFFFFFu, m, o));
    if (lane == 0) s_red[wid] = m;
    __syncthreads();
    if (wid == 0) {
        float v = (lane < NTHREADS / 32) ? s_red[lane] : 0.0f;
        #pragma unroll
        for (int o = 16; o > 0; o >>= 1)
            v = fmaxf(v, __shfl_xor_sync(0xFFFFFFFFu, v, o));
        if (lane == 0) s_red[0] = v;
    }
    __syncthreads();
    float inv_denom = 1.0f / __fadd_rn(s_red[0], 1e-8f);
    __syncthreads();

    // ---------------- Phase 2: focal loss^2 from smem (2-way ILP) ----------
    // fl^2 = d^2 * base^(2g), 2g = 4*exp(-d) = ex2(2 - d*log2(e))
    const float L2E = 1.4426950408889634f;          // log2(e)
    float sum = 0.0f;
    int i = threadIdx.x;
    for (; i + NTHREADS < cnt; i += 2 * NTHREADS) {
        float da = s_dist[i];
        float db = s_dist[i + NTHREADS];
        float Ga = ex2_ap(fmaf(-L2E, da, 2.0f));
        float Gb = ex2_ap(fmaf(-L2E, db, 2.0f));
        float ba = 1.0f - sqrt_ap(da * inv_denom);
        float bb = 1.0f - sqrt_ap(db * inv_denom);
        float wa = ex2_ap(Ga * lg2_ap(ba));
        float wb = ex2_ap(Gb * lg2_ap(bb));
        sum = fmaf(wa, da * da, sum);
        sum = fmaf(wb, db * db, sum);
    }
    if (i < cnt) {
        float d    = s_dist[i];
        float G    = ex2_ap(fmaf(-L2E, d, 2.0f));
        float base = 1.0f - sqrt_ap(d * inv_denom);
        float w2   = ex2_ap(G * lg2_ap(base));
        sum = fmaf(w2, d * d, sum);
    }

    #pragma unroll
    for (int o = 16; o > 0; o >>= 1)
        sum += __shfl_xor_sync(0xFFFFFFFFu, sum, o);
    if (lane == 0) s_red[wid] = sum;
    __syncthreads();
    if (wid == 0) {
        float v = (lane < NTHREADS / 32) ? s_red[lane] : 0.0f;
        #pragma unroll
        for (int o = 16; o > 0; o >>= 1)
            v += __shfl_xor_sync(0xFFFFFFFFu, v, o);
        if (lane == 0) g_partials[blockIdx.x] = v;
    }

    // ---------------- Last block finishes (deterministic) ----------------
    __shared__ unsigned s_ticket;
    __threadfence();
    if (threadIdx.x == 0)
        s_ticket = atomicAdd(&g_ticket, 1u);
    __syncthreads();
    if (s_ticket == BLOCKS - 1) {
        __threadfence();
        float fs = 0.0f;
        for (int k = threadIdx.x; k < BLOCKS; k += NTHREADS)
            fs += g_partials[k];
        #pragma unroll
        for (int o = 16; o > 0; o >>= 1)
            fs += __shfl_xor_sync(0xFFFFFFFFu, fs, o);
        __syncthreads();
        if (lane == 0) s_red[wid] = fs;
        __syncthreads();
        if (wid == 0) {
            float v = (lane < NTHREADS / 32) ? s_red[lane] : 0.0f;
            #pragma unroll
            for (int o = 16; o > 0; o >>= 1)
                v += __shfl_xor_sync(0xFFFFFFFFu, v, o);
            if (lane == 0) {
                out[0] = sqrtf(v / (float)B);
                g_ticket = 0;
            }
        }
    }
}

// ---------------------------------------------------------------------------
extern "C" void kernel_launch(void* const* d_in, const int* in_sizes, int n_in,
                              void* d_out, int out_size) {
    const float* inp = (const float*)d_in[0];   // (B,3) pred ECEF
    const float* tgt = (const float*)d_in[1];   // (B,3) lat/lon/h
    int B = in_sizes[0] / 3;
    float* out = (float*)d_out;

    k_fused<<<BLOCKS, NTHREADS>>>(inp, tgt, out, B);
}